// round 2
// baseline (speedup 1.0000x reference)
#include <cuda_runtime.h>
#include <cuda_bf16.h>

// Problem: N=8192 bodies in BOX=112, radii in [0.5, 1.0) -> rsum < 2.0.
// Spatial grid with cell size 2.0 (56x56): all AABB-overlapping pairs are
// within a +-1 cell ring (2-cell gap => |dx| > 2.0 > rsum).
// Ordering requirement: reference compacts pairs in row-major ascending
// (i, j) order with hard cutoffs (4N broad, N narrow) -> we reproduce exact
// global ranks via per-row sorted candidate lists + row-count prefix scan.

#define MAXN  8192
#define MAXB  (4 * MAXN)
#define GDIM  56
#define NCELL (GDIM * GDIM)
#define CAP   64          // per-row candidate capacity (avg ~8, Poisson tail safe)

__device__ int    g_cellcnt[NCELL];
__device__ int    g_cellfill[NCELL];
__device__ int    g_cellstart[NCELL];
__device__ float4 g_cellbody[MAXN];     // (x, y, r, body index as bits)
__device__ int    g_bodycell[MAXN];
__device__ int    g_rowcnt[MAXN];
__device__ int    g_rowoff[MAXN];
__device__ int    g_total;
__device__ int    g_rowbuf[MAXN * CAP]; // sorted j's per row
__device__ int    g_pair[MAXB];         // packed (i<<16)|j
__device__ int    g_hit[MAXB];
__device__ float2 g_delta[MAXB];        // 0.5 * penetration vector

__device__ __forceinline__ int cell_of(float x, float y) {
    int cx = (int)(x * 0.5f);
    int cy = (int)(y * 0.5f);
    cx = max(0, min(GDIM - 1, cx));
    cy = max(0, min(GDIM - 1, cy));
    return cy * GDIM + cx;
}

// --------------------------------------------------------------------------
__global__ void zero_cells_kernel() {
    int t = blockIdx.x * blockDim.x + threadIdx.x;
    if (t < NCELL) g_cellcnt[t] = 0;
}

// --------------------------------------------------------------------------
__global__ void hist_kernel(const float2* __restrict__ c, int n) {
    int i = blockIdx.x * blockDim.x + threadIdx.x;
    if (i >= n) return;
    float2 ci = c[i];
    int cell = cell_of(ci.x, ci.y);
    g_bodycell[i] = cell;
    atomicAdd(&g_cellcnt[cell], 1);
}

// --------------------------------------------------------------------------
// Exclusive scan over NCELL cell counts (single block, 1024 thr x 4 elems).
__global__ void scan_cells_kernel() {
    __shared__ int s[1024];
    const int t = threadIdx.x;
    const int base = t * 4;
    int local[4];
    int sum = 0;
    #pragma unroll
    for (int k = 0; k < 4; k++) {
        int idx = base + k;
        int v = (idx < NCELL) ? g_cellcnt[idx] : 0;
        local[k] = sum;
        sum += v;
    }
    s[t] = sum;
    __syncthreads();
    for (int o = 1; o < 1024; o <<= 1) {
        int x = (t >= o) ? s[t - o] : 0;
        __syncthreads();
        s[t] += x;
        __syncthreads();
    }
    int excl = s[t] - sum;
    #pragma unroll
    for (int k = 0; k < 4; k++) {
        int idx = base + k;
        if (idx < NCELL) {
            int st = excl + local[k];
            g_cellstart[idx] = st;
            g_cellfill[idx]  = st;
        }
    }
}

// --------------------------------------------------------------------------
__global__ void scatter_kernel(const float2* __restrict__ c,
                               const float*  __restrict__ r, int n) {
    int i = blockIdx.x * blockDim.x + threadIdx.x;
    if (i >= n) return;
    float2 ci = c[i];
    int cell = g_bodycell[i];
    int slot = atomicAdd(&g_cellfill[cell], 1);
    g_cellbody[slot] = make_float4(ci.x, ci.y, r[i], __int_as_float(i));
}

// --------------------------------------------------------------------------
// Per-body grid query: gather AABB-overlapping j > i from 3x3 cell ring,
// insertion-sort ascending, stash to rowbuf, write row count.
__global__ void stash_kernel(const float2* __restrict__ c,
                             const float*  __restrict__ r, int n) {
    int i = blockIdx.x * blockDim.x + threadIdx.x;
    if (i >= n) return;
    float2 ci = c[i];
    float  ri = r[i];
    int cx = max(0, min(GDIM - 1, (int)(ci.x * 0.5f)));
    int cy = max(0, min(GDIM - 1, (int)(ci.y * 0.5f)));

    int jl[CAP];
    int cnt = 0;
    for (int dy = -1; dy <= 1; dy++) {
        int yy = cy + dy;
        if (yy < 0 || yy >= GDIM) continue;
        for (int dx = -1; dx <= 1; dx++) {
            int xx = cx + dx;
            if (xx < 0 || xx >= GDIM) continue;
            int cell = yy * GDIM + xx;
            int st = g_cellstart[cell];
            int en = st + g_cellcnt[cell];
            for (int k = st; k < en; k++) {
                float4 b = g_cellbody[k];
                int j = __float_as_int(b.w);
                if (j <= i) continue;
                float rs = ri + b.z;
                if (fabsf(ci.x - b.x) <= rs && fabsf(ci.y - b.y) <= rs) {
                    if (cnt < CAP) jl[cnt] = j;
                    cnt++;
                }
            }
        }
    }
    if (cnt > CAP) cnt = CAP;
    // insertion sort ascending (tiny list)
    for (int a = 1; a < cnt; a++) {
        int v = jl[a];
        int b = a - 1;
        while (b >= 0 && jl[b] > v) { jl[b + 1] = jl[b]; b--; }
        jl[b + 1] = v;
    }
    g_rowcnt[i] = cnt;
    for (int k = 0; k < cnt; k++) g_rowbuf[i * CAP + k] = jl[k];
}

// --------------------------------------------------------------------------
// Exclusive scan of row counts (single block, 1024 thr x 8 elems).
__global__ void scan_rows_kernel(int n) {
    __shared__ int s[1024];
    const int t = threadIdx.x;
    const int base = t * 8;
    int local[8];
    int sum = 0;
    #pragma unroll
    for (int k = 0; k < 8; k++) {
        int idx = base + k;
        int v = (idx < n) ? g_rowcnt[idx] : 0;
        local[k] = sum;
        sum += v;
    }
    s[t] = sum;
    __syncthreads();
    for (int o = 1; o < 1024; o <<= 1) {
        int x = (t >= o) ? s[t - o] : 0;
        __syncthreads();
        s[t] += x;
        __syncthreads();
    }
    int excl = s[t] - sum;
    #pragma unroll
    for (int k = 0; k < 8; k++) {
        int idx = base + k;
        if (idx < n) g_rowoff[idx] = excl + local[k];
    }
    if (t == 1023) g_total = s[1023];
}

// --------------------------------------------------------------------------
// Emit packed pairs at exact row-major ranks + fused narrow phase.
__global__ void emit_narrow_kernel(const float2* __restrict__ c,
                                   const float*  __restrict__ r, int n,
                                   const int* __restrict__ d_lb) {
    int i = blockIdx.x * blockDim.x + threadIdx.x;
    if (i >= n) return;
    const int limitb = min(*d_lb, MAXB);
    int off = g_rowoff[i];
    int cnt = g_rowcnt[i];
    if (off >= limitb) return;
    float2 ci = c[i];
    float  ri = r[i];
    for (int k = 0; k < cnt; k++) {
        int slot = off + k;
        if (slot >= limitb) break;
        int j = g_rowbuf[i * CAP + k];
        float2 cj = c[j];
        float dx = cj.x - ci.x;
        float dy = cj.y - ci.y;
        float dist = sqrtf(dx * dx + dy * dy + 1e-12f);
        float depth = ri + r[j] - dist;
        int hit = 0;
        float2 delta = make_float2(0.f, 0.f);
        if (depth > 0.f) {
            hit = 1;
            float sc = 0.5f * depth / dist;
            delta = make_float2(sc * dx, sc * dy);
        }
        g_pair[slot]  = (i << 16) | j;
        g_hit[slot]   = hit;
        g_delta[slot] = delta;
    }
}

// --------------------------------------------------------------------------
// Single-block scan of hit flags + ordered scatter of first limit_narrow hits.
__global__ void resolve_kernel(float* __restrict__ out,
                               const int* __restrict__ d_lb,
                               const int* __restrict__ d_ln) {
    __shared__ int s[1024];
    const int t = threadIdx.x;
    const int limitb = min(*d_lb, MAXB);
    const int ln  = *d_ln;
    const int tot = min(g_total, limitb);
    const int items = (limitb + 1023) / 1024;
    const int start = t * items;
    const int end   = min(start + items, tot);

    int sum = 0;
    for (int k = start; k < end; k++) sum += g_hit[k];
    s[t] = sum;
    __syncthreads();
    for (int o = 1; o < 1024; o <<= 1) {
        int x = (t >= o) ? s[t - o] : 0;
        __syncthreads();
        s[t] += x;
        __syncthreads();
    }
    int rank = s[t] - sum;   // exclusive prefix for this thread's range
    for (int k = start; k < end; k++) {
        if (g_hit[k]) {
            if (rank < ln) {
                int p = g_pair[k];
                int i = p >> 16;
                int j = p & 0xFFFF;
                float2 d = g_delta[k];
                atomicAdd(&out[2 * i + 0], -d.x);
                atomicAdd(&out[2 * i + 1], -d.y);
                atomicAdd(&out[2 * j + 0],  d.x);
                atomicAdd(&out[2 * j + 1],  d.y);
            }
            rank++;
        }
    }
}

// --------------------------------------------------------------------------
extern "C" void kernel_launch(void* const* d_in, const int* in_sizes, int n_in,
                              void* d_out, int out_size) {
    const float2* centers = (const float2*)d_in[0];
    const float*  radii   = (const float*)d_in[1];
    const int*    d_lb    = (const int*)d_in[2];
    const int*    d_ln    = (const int*)d_in[3];
    const int n = in_sizes[1];            // number of bodies
    float* out = (float*)d_out;

    cudaMemcpyAsync(out, centers, (size_t)n * 2 * sizeof(float),
                    cudaMemcpyDeviceToDevice);

    const int nb = (n + 255) / 256;
    zero_cells_kernel<<<(NCELL + 255) / 256, 256>>>();
    hist_kernel<<<nb, 256>>>(centers, n);
    scan_cells_kernel<<<1, 1024>>>();
    scatter_kernel<<<nb, 256>>>(centers, radii, n);
    stash_kernel<<<nb, 256>>>(centers, radii, n);
    scan_rows_kernel<<<1, 1024>>>(n);
    emit_narrow_kernel<<<nb, 256>>>(centers, radii, n, d_lb);
    resolve_kernel<<<1, 1024>>>(out, d_lb, d_ln);
}